// round 14
// baseline (speedup 1.0000x reference)
#include <cuda_runtime.h>
#include <cstdint>

// VectorQuantizer: input (16, 64, 8192) fp32, codebook (1024, 64) fp32
// score(n,k) = 0.5*||e_k||^2 - x_n . e_k   (argmin-equivalent to ||x - e||^2)
//
// R14: tensor filter (mma.sync m16n8k8 tf32, 3-term split) + exact top-2
// rescore (R12/R13-verified). Fixes vs R13:
//  - term-major MMA order: dependent-MMA spacing 1 -> 8
//  - A-fragments built ONCE into registers (chunk-invariant)

#define Dd 64
#define Kk 1024
#define Tt 8192
#define Nn (16 * 8192)
#define TPB 256
#define TOKS 128
#define NCHUNK 16
#define BCHUNK 16384             // 64 codes: 8n*8kk*32lanes*8B

#define XSTRIDE 68               // floats per token row (64 + 4 pad)
#define XOFF 0
#define XBYTES (TOKS * XSTRIDE * 4)      // 34816
#define BOFF0 XBYTES
#define BOFF1 (BOFF0 + 2 * BCHUNK)       // 67584
#define HOFFS (BOFF1 + 2 * BCHUNK)       // 100352
#define SMEM_BYTES (HOFFS + 4096)        // 104448

#define EB 2e-3f

__device__ float g_half[Kk];
__device__ unsigned long long g_ebH[NCHUNK * 2048];   // B frag image, tf32 hi
__device__ unsigned long long g_ebL[NCHUNK * 2048];   // B frag image, tf32 lo

typedef unsigned long long u64;
typedef uint32_t u32;

__device__ __forceinline__ u32 f2tf(float x) {
    u32 r; asm("cvt.rna.tf32.f32 %0, %1;" : "=r"(r) : "f"(x)); return r;
}
__device__ __forceinline__ uint32_t s2u(const void* p) {
    uint32_t a;
    asm("{ .reg .u64 t; cvta.to.shared.u64 t, %1; cvt.u32.u64 %0, t; }" : "=r"(a) : "l"(p));
    return a;
}
__device__ __forceinline__ void cp16(uint32_t dst, const void* src) {
    uint64_t g = __cvta_generic_to_global(src);
    asm volatile("cp.async.cg.shared.global [%0], [%1], 16;" :: "r"(dst), "l"(g) : "memory");
}
__device__ __forceinline__ void cp_commit() { asm volatile("cp.async.commit_group;" ::: "memory"); }
template <int N>
__device__ __forceinline__ void cp_wait() { asm volatile("cp.async.wait_group %0;" :: "n"(N) : "memory"); }

__device__ __forceinline__ void mma8(float* d, const u32* a, u32 b0, u32 b1) {
    asm volatile(
        "mma.sync.aligned.m16n8k8.row.col.f32.tf32.tf32.f32 "
        "{%0,%1,%2,%3}, {%4,%5,%6,%7}, {%8,%9}, {%0,%1,%2,%3};"
        : "+f"(d[0]), "+f"(d[1]), "+f"(d[2]), "+f"(d[3])
        : "r"(a[0]), "r"(a[1]), "r"(a[2]), "r"(a[3]), "r"(b0), "r"(b1));
}

__device__ __forceinline__ void upd(float& s1, int& i1, float& s2, int& i2, float s, int i) {
    if (s < s1) { s2 = s1; i2 = i1; s1 = s; i1 = i; }
    else if (s < s2) { s2 = s; i2 = i; }
}
__device__ __forceinline__ void merge2(float& s1, int& i1, float& s2, int& i2, int off) {
    float t1 = __shfl_xor_sync(0xffffffffu, s1, off);
    float t2 = __shfl_xor_sync(0xffffffffu, s2, off);
    int   j1 = __shfl_xor_sync(0xffffffffu, i1, off);
    int   j2 = __shfl_xor_sync(0xffffffffu, i2, off);
    bool tf = (t1 < s1) || (t1 == s1 && j1 < i1);
    float n1 = tf ? t1 : s1;  int m1 = tf ? j1 : i1;
    float ca = tf ? s1 : t1;  int ia = tf ? i1 : j1;
    float cbv = tf ? t2 : s2; int ib = tf ? j2 : i2;
    bool af = (ca < cbv) || (ca == cbv && ia < ib);
    s1 = n1; i1 = m1;
    s2 = af ? ca : cbv; i2 = af ? ia : ib;
}

// ---- prologue: 0.5||e||^2 + tf32 hi/lo B-fragment images (verified) ----
__global__ void vq_pre(const float* __restrict__ cb) {
    int k = blockIdx.x * blockDim.x + threadIdx.x;
    if (k >= Kk) return;
    const float* row = cb + k * Dd;
    float s = 0.f;
#pragma unroll
    for (int d = 0; d < Dd; d++) s += row[d] * row[d];
    g_half[k] = 0.5f * s;
    int c = k >> 6, nn = (k >> 3) & 7, cq = k & 7;
#pragma unroll
    for (int kk = 0; kk < 8; kk++) {
#pragma unroll
        for (int rq = 0; rq < 4; rq++) {
            float e0 = row[kk * 8 + rq];
            float e1 = row[kk * 8 + rq + 4];
            u32 h0 = f2tf(e0), h1 = f2tf(e1);
            u32 l0 = f2tf(e0 - __uint_as_float(h0));
            u32 l1 = f2tf(e1 - __uint_as_float(h1));
            int idx = ((c * 8 + nn) * 8 + kk) * 32 + cq * 4 + rq;
            g_ebH[idx] = ((u64)h1 << 32) | h0;
            g_ebL[idx] = ((u64)l1 << 32) | l0;
        }
    }
}

__global__ __launch_bounds__(TPB, 1)
void vq_main(const float* __restrict__ input, const float* __restrict__ cb,
             float* __restrict__ out, float* __restrict__ out_idx) {
    extern __shared__ __align__(16) unsigned char smem[];
    const uint32_t sb = s2u(smem);
    const int tid = threadIdx.x, wid = tid >> 5, lane = tid & 31;
    const int r4 = lane >> 2, c4b = lane & 3;
    const int tile = blockIdx.x, b = tile >> 6, tb = (tile & 63) * TOKS;

    float* Xs = (float*)(smem + XOFF);
    float* sH = (float*)(smem + HOFFS);

    // prefetch B chunk 0 (hi + lo)
#pragma unroll
    for (int s = 0; s < 4; s++) {
        int i = tid + s * TPB;
        cp16(sb + BOFF0 + i * 16, (const char*)g_ebH + i * 16);
        cp16(sb + BOFF0 + BCHUNK + i * 16, (const char*)g_ebL + i * 16);
    }
    cp_commit();

    // stage plain X (padded rows), coalesced global reads
    {
        const float* inb = input + (size_t)b * Dd * Tt + tb;
#pragma unroll 8
        for (int it = 0; it < 32; it++) {
            int idx = tid + it * TPB;
            int d = idx >> 7, t = idx & 127;
            Xs[t * XSTRIDE + d] = inb[(size_t)d * Tt + t];
        }
    }
    for (int i = tid; i < Kk; i += TPB) sH[i] = g_half[i];
    __syncthreads();

    // build A fragments ONCE (chunk-invariant): 8 kk-steps, hi+lo
    u32 ah[8][4], al[8][4];
    {
        const float* Xf0 = Xs + (wid * 16 + r4) * XSTRIDE + c4b;   // row r4
        const float* Xf1 = Xf0 + 8 * XSTRIDE;                      // row r4+8
#pragma unroll
        for (int kk = 0; kk < 8; kk++) {
            float x0 = Xf0[kk * 8];
            float x1 = Xf1[kk * 8];
            float x2 = Xf0[kk * 8 + 4];
            float x3 = Xf1[kk * 8 + 4];
            ah[kk][0] = f2tf(x0); al[kk][0] = f2tf(x0 - __uint_as_float(ah[kk][0]));
            ah[kk][1] = f2tf(x1); al[kk][1] = f2tf(x1 - __uint_as_float(ah[kk][1]));
            ah[kk][2] = f2tf(x2); al[kk][2] = f2tf(x2 - __uint_as_float(ah[kk][2]));
            ah[kk][3] = f2tf(x3); al[kk][3] = f2tf(x3 - __uint_as_float(ah[kk][3]));
        }
    }

    // top-2 approx per D-fragment row pair
    float s1a = 3.4e38f, s2a = 3.4e38f, s1b = 3.4e38f, s2b = 3.4e38f;
    int   i1a = 0, i2a = 0, i1b = 0, i2b = 0;

    for (int c = 0; c < NCHUNK; c++) {
        const int st = c & 1;
        if (c + 1 < NCHUNK) {
            uint32_t nxt = sb + (st ? BOFF0 : BOFF1);
            const char* shp = (const char*)g_ebH + (size_t)(c + 1) * BCHUNK;
            const char* slp = (const char*)g_ebL + (size_t)(c + 1) * BCHUNK;
#pragma unroll
            for (int s = 0; s < 4; s++) {
                int i = tid + s * TPB;
                cp16(nxt + i * 16, shp + i * 16);
                cp16(nxt + BCHUNK + i * 16, slp + i * 16);
            }
            cp_commit();
            cp_wait<1>();
        } else {
            cp_wait<0>();
        }
        __syncthreads();

        const unsigned char* bhC = smem + (st ? BOFF1 : BOFF0);
        const unsigned char* blC = bhC + BCHUNK;

        float d[8][4];
#pragma unroll
        for (int n = 0; n < 8; n++)
#pragma unroll
            for (int j = 0; j < 4; j++) d[n][j] = 0.f;

#pragma unroll
        for (int kk = 0; kk < 8; kk++) {
            // load all 8 hi B-frags for this kk, then run term-major MMAs:
            // dependent MMAs on the same d[n] are spaced 8 apart.
            u64 h[8];
#pragma unroll
            for (int n = 0; n < 8; n++)
                h[n] = *(const u64*)(bhC + (u32)(((n * 8 + kk) * 32 + lane) * 8));
#pragma unroll
            for (int n = 0; n < 8; n++) mma8(d[n], ah[kk], (u32)h[n], (u32)(h[n] >> 32));
#pragma unroll
            for (int n = 0; n < 8; n++) mma8(d[n], al[kk], (u32)h[n], (u32)(h[n] >> 32));
            u64 l[8];
#pragma unroll
            for (int n = 0; n < 8; n++)
                l[n] = *(const u64*)(blC + (u32)(((n * 8 + kk) * 32 + lane) * 8));
#pragma unroll
            for (int n = 0; n < 8; n++) mma8(d[n], ah[kk], (u32)l[n], (u32)(l[n] >> 32));
        }

        // fold tile scores into per-row top-2
#pragma unroll
        for (int n = 0; n < 8; n++) {
            int cb0 = c * 64 + n * 8 + 2 * c4b;
            float2 hp = *(const float2*)(sH + cb0);
            upd(s1a, i1a, s2a, i2a, hp.x - d[n][0], cb0);
            upd(s1a, i1a, s2a, i2a, hp.y - d[n][1], cb0 + 1);
            upd(s1b, i1b, s2b, i2b, hp.x - d[n][2], cb0);
            upd(s1b, i1b, s2b, i2b, hp.y - d[n][3], cb0 + 1);
        }
        __syncthreads();
    }

    // merge across the 4 lanes sharing each row
    merge2(s1a, i1a, s2a, i2a, 1); merge2(s1a, i1a, s2a, i2a, 2);
    merge2(s1b, i1b, s2b, i2b, 1); merge2(s1b, i1b, s2b, i2b, 2);

    // exact rescore: lane q handles (q<2 ? rowA : rowB), candidate (q&1)
    const int q = c4b;
    const int myrow = (q < 2) ? r4 : r4 + 8;
    const int cand = (q == 0) ? i1a : (q == 1) ? i2a : (q == 2) ? i1b : i2b;
    const float s2app = (q < 2) ? s2a : s2b;
    const int tloc = wid * 16 + myrow;
    const float4* xr = (const float4*)(Xs + tloc * XSTRIDE);

    float sex;
    {
        const float4* er = (const float4*)(cb + (size_t)cand * 64);
        float a0 = 0.f, a1 = 0.f, a2 = 0.f, a3 = 0.f;
#pragma unroll
        for (int i = 0; i < 16; i += 4) {
            float4 xv, ev;
            xv = xr[i];     ev = er[i];     a0 = fmaf(xv.x, ev.x, fmaf(xv.y, ev.y, fmaf(xv.z, ev.z, fmaf(xv.w, ev.w, a0))));
            xv = xr[i + 1]; ev = er[i + 1]; a1 = fmaf(xv.x, ev.x, fmaf(xv.y, ev.y, fmaf(xv.z, ev.z, fmaf(xv.w, ev.w, a1))));
            xv = xr[i + 2]; ev = er[i + 2]; a2 = fmaf(xv.x, ev.x, fmaf(xv.y, ev.y, fmaf(xv.z, ev.z, fmaf(xv.w, ev.w, a2))));
            xv = xr[i + 3]; ev = er[i + 3]; a3 = fmaf(xv.x, ev.x, fmaf(xv.y, ev.y, fmaf(xv.z, ev.z, fmaf(xv.w, ev.w, a3))));
        }
        sex = sH[cand] - ((a0 + a1) + (a2 + a3));
    }
    float po = __shfl_xor_sync(0xffffffffu, sex, 1);
    int   pc = __shfl_xor_sync(0xffffffffu, cand, 1);

    if ((q & 1) == 0) {
        bool mine = (sex < po) || (sex == po && cand < pc);
        int ichosen = mine ? cand : pc;
        float schosen = mine ? sex : po;
        if (!(schosen < s2app - EB)) {
            // rare: margin violated -> exact full scan (first-occurrence argmin)
            float bsf = 3.4e38f; int bif = 0;
            for (int k2 = 0; k2 < Kk; k2++) {
                const float4* e2 = (const float4*)(cb + (size_t)k2 * 64);
                float a0 = 0.f, a1 = 0.f, a2 = 0.f, a3 = 0.f;
#pragma unroll 4
                for (int i = 0; i < 16; i += 4) {
                    float4 xv, ev;
                    xv = xr[i];     ev = e2[i];     a0 = fmaf(xv.x, ev.x, fmaf(xv.y, ev.y, fmaf(xv.z, ev.z, fmaf(xv.w, ev.w, a0))));
                    xv = xr[i + 1]; ev = e2[i + 1]; a1 = fmaf(xv.x, ev.x, fmaf(xv.y, ev.y, fmaf(xv.z, ev.z, fmaf(xv.w, ev.w, a1))));
                    xv = xr[i + 2]; ev = e2[i + 2]; a2 = fmaf(xv.x, ev.x, fmaf(xv.y, ev.y, fmaf(xv.z, ev.z, fmaf(xv.w, ev.w, a2))));
                    xv = xr[i + 3]; ev = e2[i + 3]; a3 = fmaf(xv.x, ev.x, fmaf(xv.y, ev.y, fmaf(xv.z, ev.z, fmaf(xv.w, ev.w, a3))));
                }
                float ss = sH[k2] - ((a0 + a1) + (a2 + a3));
                if (ss < bsf) { bsf = ss; bif = k2; }
            }
            ichosen = bif;
        }
        const int tglob = tb + tloc;
        float* ob = out + (size_t)b * Dd * Tt + tglob;
        const float4* cv = (const float4*)(cb + (size_t)ichosen * 64);
#pragma unroll
        for (int i = 0; i < 16; i++) {
            float4 v = cv[i];
            ob[(size_t)(4 * i + 0) * Tt] = v.x;
            ob[(size_t)(4 * i + 1) * Tt] = v.y;
            ob[(size_t)(4 * i + 2) * Tt] = v.z;
            ob[(size_t)(4 * i + 3) * Tt] = v.w;
        }
        if (out_idx != nullptr) out_idx[(size_t)b * Tt + tglob] = (float)ichosen;
    }
}

extern "C" void kernel_launch(void* const* d_in, const int* in_sizes, int n_in,
                              void* d_out, int out_size) {
    const float* input = (const float*)d_in[0];   // (16, 64, 8192) fp32
    const float* cb    = (const float*)d_in[1];   // (1024, 64) fp32
    float* out = (float*)d_out;

    float* out_idx = nullptr;
    if (out_size >= (int)((long)Nn * Dd + Nn)) out_idx = out + (long)Nn * Dd;

    cudaFuncSetAttribute(vq_main, cudaFuncAttributeMaxDynamicSharedMemorySize, SMEM_BYTES);

    vq_pre<<<(Kk + 127) / 128, 128>>>(cb);
    vq_main<<<Nn / TOKS, TPB, SMEM_BYTES>>>(input, cb, out, out_idx);
}

// round 15
// speedup vs baseline: 2.1437x; 2.1437x over previous
#include <cuda_runtime.h>
#include <cstdint>

// VectorQuantizer: input (16, 64, 8192) fp32, codebook (1024, 64) fp32
// score(n,k) = 0.5*||e_k||^2 - x_n . e_k   (argmin-equivalent to ||x - e||^2)
//
// R15 = R8 champion (8x8 fp32x2 register-tile GEMM, mono-key argmin) with the
// inner loop manually software-pipelined: ping-pong register buffers load
// iteration i+1's X/E fragments before issuing iteration i's 64 FMAs, hiding
// the 29-cyc LDS latency that left the FMA pipe 35% idle at 2 warps/SMSP.

#define Dd 64
#define Kk 1024
#define Bb 16
#define Tt 8192
#define Nn (Bb * Tt)             // 131072 tokens
#define TPB 128
#define TOK_PER_CTA 128
#define CK 64                    // codes per chunk
#define NCHUNK (Kk / CK)         // 16

#define GSTRIDE 2064             // 8-entry group: 32 dpairs*64B + 16B pad (== 16 mod 128)
#define CHUNK_BYTES (8 * GSTRIDE)        // 16512
#define XOFF 0                   // X image: 16 groups
#define XBYTES (16 * GSTRIDE)            // 33024
#define EOFF0 XBYTES
#define EOFF1 (EOFF0 + CHUNK_BYTES)      // 49536
#define HOFF  (EOFF1 + CHUNK_BYTES)      // 66048
#define IOFF  (HOFF + 4096)              // 70144
#define SMEM_BYTES (IOFF + 512)          // 70656

__device__ float g_half[Kk];
__device__ __align__(16) unsigned char g_cbT[NCHUNK * CHUNK_BYTES];

typedef unsigned long long u64;

// ---- packed f32x2 helpers ----
__device__ __forceinline__ u64 pk2(float a, float b) {
    u64 r; asm("mov.b64 %0, {%1, %2};" : "=l"(r) : "f"(a), "f"(b)); return r;
}
__device__ __forceinline__ void fma2(u64& acc, u64 a, u64 b) {
    asm("fma.rn.f32x2 %0, %1, %2, %0;" : "+l"(acc) : "l"(a), "l"(b));
}
__device__ __forceinline__ float hsum2(u64 v) {
    float lo, hi; asm("mov.b64 {%0, %1}, %2;" : "=f"(lo), "=f"(hi) : "l"(v));
    return lo + hi;
}
// order-preserving float -> u32 (exact, bijective)
__device__ __forceinline__ uint32_t mono(float f) {
    uint32_t b = __float_as_uint(f);
    return b ^ (uint32_t)(((int32_t)b >> 31) | 0x80000000);
}

// ---- cp.async helpers ----
__device__ __forceinline__ void cp16(uint32_t dst, const void* src) {
    uint64_t g = __cvta_generic_to_global(src);
    asm volatile("cp.async.cg.shared.global [%0], [%1], 16;" :: "r"(dst), "l"(g) : "memory");
}
__device__ __forceinline__ void cp_commit() { asm volatile("cp.async.commit_group;" ::: "memory"); }
template <int N>
__device__ __forceinline__ void cp_wait() { asm volatile("cp.async.wait_group %0;" :: "n"(N) : "memory"); }

__device__ __forceinline__ uint32_t s2u(const void* p) {
    uint32_t a;
    asm("{ .reg .u64 t; cvta.to.shared.u64 t, %1; cvt.u32.u64 %0, t; }" : "=r"(a) : "l"(p));
    return a;
}

// ---- prologue: 0.5||e||^2 + padded transposed codebook image ----
__global__ void vq_pre(const float* __restrict__ cb) {
    int k = blockIdx.x * blockDim.x + threadIdx.x;
    if (k >= Kk) return;
    const float* row = cb + k * Dd;
    float s = 0.f;
    unsigned char* dst = g_cbT + (k >> 6) * CHUNK_BYTES + ((k >> 3) & 7) * GSTRIDE + (k & 7) * 8;
#pragma unroll
    for (int i = 0; i < 32; i++) {
        float a = row[2 * i], b = row[2 * i + 1];
        s += a * a + b * b;
        *(u64*)(dst + i * 64) = pk2(a, b);
    }
    g_half[k] = 0.5f * s;
}

// 64 FMA2s of one dpair-iteration: 8 x-pairs vs 8 e-pairs
__device__ __forceinline__ void fma_block(u64 (&acc)[8][8],
                                          const ulonglong2 (&x)[4],
                                          const ulonglong2 (&e)[4]) {
    u64 xv[8] = {x[0].x, x[0].y, x[1].x, x[1].y, x[2].x, x[2].y, x[3].x, x[3].y};
    u64 ev[8] = {e[0].x, e[0].y, e[1].x, e[1].y, e[2].x, e[2].y, e[3].x, e[3].y};
#pragma unroll
    for (int m = 0; m < 8; m++)
#pragma unroll
        for (int k = 0; k < 8; k++)
            fma2(acc[m][k], xv[m], ev[k]);
}

__global__ __launch_bounds__(TPB, 2)
void vq_main(const float* __restrict__ input, const float* __restrict__ cb,
             float* __restrict__ out, float* __restrict__ out_idx) {
    extern __shared__ __align__(16) unsigned char smem[];
    const uint32_t sb = s2u(smem);

    const int tid = threadIdx.x;
    const int kl  = tid & 7;        // code-group lane (8 codes)
    const int ml  = tid >> 3;       // token-group (8 tokens)
    const int tile = blockIdx.x;    // 0..1023
    const int b    = tile >> 6;
    const int tb   = (tile & 63) * TOK_PER_CTA;

    // prefetch codebook chunk 0
#pragma unroll
    for (int s = 0; s < 9; s++) {
        int idx = tid + s * TPB;
        if (idx < CHUNK_BYTES / 16)
            cp16(sb + EOFF0 + idx * 16, g_cbT + idx * 16);
    }
    cp_commit();

    // stage X tile: token t = tb + tid, packed pairs along D
    {
        const float* inb = input + (size_t)b * Dd * Tt + tb + tid;
        unsigned char* xdst = smem + XOFF + (tid >> 3) * GSTRIDE + (tid & 7) * 8;
#pragma unroll 8
        for (int i = 0; i < 32; i++) {
            float a = inb[(size_t)(2 * i) * Tt];
            float c = inb[(size_t)(2 * i + 1) * Tt];
            *(u64*)(xdst + i * 64) = pk2(a, c);
        }
    }
    {
        float* sH = (float*)(smem + HOFF);
#pragma unroll
        for (int i = tid; i < Kk; i += TPB) sH[i] = g_half[i];
    }

    u64 best[8];
#pragma unroll
    for (int m = 0; m < 8; m++) best[m] = 0xFFFFFFFFFFFFFFFFull;

    const unsigned char* Xb = smem + XOFF + ml * GSTRIDE;
    const float* sH = (const float*)(smem + HOFF);

    for (int c = 0; c < NCHUNK; c++) {
        const int st = c & 1;
        if (c + 1 < NCHUNK) {
            const uint32_t nxt = sb + (st ? EOFF0 : EOFF1);
            const unsigned char* src = g_cbT + (size_t)(c + 1) * CHUNK_BYTES;
#pragma unroll
            for (int s = 0; s < 9; s++) {
                int idx = tid + s * TPB;
                if (idx < CHUNK_BYTES / 16)
                    cp16(nxt + idx * 16, src + idx * 16);
            }
            cp_commit();
            cp_wait<1>();
        } else {
            cp_wait<0>();
        }
        __syncthreads();

        const unsigned char* Eb = smem + (st ? EOFF1 : EOFF0) + kl * GSTRIDE;
        const ulonglong2* XbU = (const ulonglong2*)Xb;   // 4 per dpair-iteration
        const ulonglong2* EbU = (const ulonglong2*)Eb;

        u64 acc[8][8];
#pragma unroll
        for (int m = 0; m < 8; m++)
#pragma unroll
            for (int k = 0; k < 8; k++) acc[m][k] = 0;

        // ---- software-pipelined mainloop: loads for i+1 precede FMAs of i ----
        ulonglong2 xA[4], eA[4], xB[4], eB[4];
#pragma unroll
        for (int j = 0; j < 4; j++) { xA[j] = XbU[j]; eA[j] = EbU[j]; }
#pragma unroll 2
        for (int i = 0; i < 32; i += 2) {
#pragma unroll
            for (int j = 0; j < 4; j++) {           // load i+1
                xB[j] = XbU[(i + 1) * 4 + j];
                eB[j] = EbU[(i + 1) * 4 + j];
            }
            fma_block(acc, xA, eA);                 // compute i
#pragma unroll
            for (int j = 0; j < 4; j++) {           // load i+2 (i=30 -> safe OOB in smem)
                xA[j] = XbU[(i + 2) * 4 + j];
                eA[j] = EbU[(i + 2) * 4 + j];
            }
            fma_block(acc, xB, eB);                 // compute i+1
        }

        // fold tile into per-token best keys
        const int cbase = c * CK + kl * 8;
        float hs[8];
#pragma unroll
        for (int k = 0; k < 8; k++) hs[k] = sH[cbase + k];
#pragma unroll
        for (int m = 0; m < 8; m++) {
#pragma unroll
            for (int k = 0; k < 8; k++) {
                float s = hs[k] - hsum2(acc[m][k]);
                u64 key = ((u64)mono(s) << 32) | (uint32_t)(cbase + k);
                if (key < best[m]) best[m] = key;
            }
        }
        __syncthreads();   // protect E buffer before next prefetch lands
    }

    // reduce across the 8 code-lanes (same token rows)
#pragma unroll
    for (int off = 1; off < 8; off <<= 1) {
#pragma unroll
        for (int m = 0; m < 8; m++) {
            u64 o = __shfl_xor_sync(0xffffffffu, best[m], off);
            if (o < best[m]) best[m] = o;
        }
    }
    int* sIdx = (int*)(smem + IOFF);
    if (kl == 0) {
#pragma unroll
        for (int m = 0; m < 8; m++) sIdx[ml * 8 + m] = (int)(best[m] & 0xFFFFFFFFu);
    }
    __syncthreads();

    // scatter: thread tid owns token tb + tid
    {
        const int bidx = sIdx[tid];
        const int t = tb + tid;
        float* ob = out + (size_t)b * Dd * Tt + t;
        const float4* cv = (const float4*)(cb + (size_t)bidx * Dd);
#pragma unroll
        for (int i = 0; i < Dd / 4; i++) {
            float4 v = cv[i];
            ob[(size_t)(4 * i + 0) * Tt] = v.x;
            ob[(size_t)(4 * i + 1) * Tt] = v.y;
            ob[(size_t)(4 * i + 2) * Tt] = v.z;
            ob[(size_t)(4 * i + 3) * Tt] = v.w;
        }
        if (out_idx != nullptr) out_idx[(size_t)b * Tt + t] = (float)bidx;
    }
}

extern "C" void kernel_launch(void* const* d_in, const int* in_sizes, int n_in,
                              void* d_out, int out_size) {
    const float* input = (const float*)d_in[0];   // (16, 64, 8192) fp32
    const float* cb    = (const float*)d_in[1];   // (1024, 64) fp32
    float* out = (float*)d_out;

    float* out_idx = nullptr;
    if (out_size >= (int)((long)Nn * Dd + Nn)) out_idx = out + (long)Nn * Dd;

    cudaFuncSetAttribute(vq_main, cudaFuncAttributeMaxDynamicSharedMemorySize, SMEM_BYTES);

    vq_pre<<<(Kk + 127) / 128, 128>>>(cb);
    vq_main<<<Nn / TOK_PER_CTA, TPB, SMEM_BYTES>>>(input, cb, out, out_idx);
}